// round 10
// baseline (speedup 1.0000x reference)
#include <cuda_runtime.h>
#include <cuda_bf16.h>
#include <cstdint>

// HashEmbedding gather: out[row,:] = embedding[hashed_ids[row],:]
// rows = 32768, D = 1024 fp32 = 256 float4 per row.
//
// R10: champion structure (R2/R8: 27.2-27.3us kernel, at the measured
// ~4.8 TB/s pure-write DRAM ceiling) with write-THROUGH stores (__stwt)
// instead of evict-first (__stcs): tests whether the L2 writeback drain
// path, not DRAM write bandwidth, is the limiter. Table reads stay
// L2-cached (reads were already fully L2-served in all measurements).
//
// Evidence for the write-ceiling model: 9 structural variants (LDG.128/
// .256, streaming hints, SW pipeline, TMA bulk, bucket dedup with 35%
// less LTS traffic) all converge at 27.2-30us == 134MB / ~4.8 TB/s.

static constexpr int D_F4 = 256;          // float4 per row
static constexpr int THREADS = 256;
static constexpr int LANES = 64;          // threads per row
static constexpr int ROWS_PER_BLK = 8;    // 4 sub-groups x 2 rows

__global__ void __launch_bounds__(THREADS)
hash_embedding_gather(const int* __restrict__ hashed_ids,
                      const float4* __restrict__ emb,
                      float4* __restrict__ out,
                      int nrows)
{
    int t    = threadIdx.x;
    int sub  = t >> 6;        // 0..3
    int lane = t & 63;        // 0..63

    int row0 = blockIdx.x * ROWS_PER_BLK + sub * 2;
    if (row0 >= nrows) return;

    // One 8-byte load fetches both ids (row0 even -> 8B aligned).
    int2 ids = *reinterpret_cast<const int2*>(hashed_ids + row0);

    const float4* __restrict__ srcA = emb + (size_t)ids.x * D_F4;
    const float4* __restrict__ srcB = emb + (size_t)ids.y * D_F4;
    float4*       __restrict__ dstA = out + (size_t)row0       * D_F4;
    float4*       __restrict__ dstB = out + (size_t)(row0 + 1) * D_F4;

    // 8 independent gathers, front-batched (MLP=8 per thread).
    float4 a0 = __ldg(srcA + lane);
    float4 a1 = __ldg(srcA + lane + LANES);
    float4 a2 = __ldg(srcA + lane + 2 * LANES);
    float4 a3 = __ldg(srcA + lane + 3 * LANES);
    float4 b0 = __ldg(srcB + lane);
    float4 b1 = __ldg(srcB + lane + LANES);
    float4 b2 = __ldg(srcB + lane + 2 * LANES);
    float4 b3 = __ldg(srcB + lane + 3 * LANES);

    // Write-through stores: bypass L2 writeback machinery; output is
    // write-once and never read. Fully coalesced 128B lines.
    __stwt(dstA + lane,             a0);
    __stwt(dstA + lane + LANES,     a1);
    __stwt(dstA + lane + 2 * LANES, a2);
    __stwt(dstA + lane + 3 * LANES, a3);
    __stwt(dstB + lane,             b0);
    __stwt(dstB + lane + LANES,     b1);
    __stwt(dstB + lane + 2 * LANES, b2);
    __stwt(dstB + lane + 3 * LANES, b3);
}

extern "C" void kernel_launch(void* const* d_in, const int* in_sizes, int n_in,
                              void* d_out, int out_size)
{
    // metadata order: input_ids (unused), hashed_ids (int32), embedding (fp32)
    const int*    hashed_ids = (const int*)d_in[1];
    const float4* emb        = (const float4*)d_in[2];
    float4*       out        = (float4*)d_out;

    int nrows = in_sizes[1];   // 32768
    int blocks = (nrows + ROWS_PER_BLK - 1) / ROWS_PER_BLK;

    hash_embedding_gather<<<blocks, THREADS>>>(hashed_ids, emb, out, nrows);
}

// round 11
// speedup vs baseline: 1.0029x; 1.0029x over previous
#include <cuda_runtime.h>
#include <cuda_bf16.h>
#include <cstdint>

// HashEmbedding gather: out[row,:] = embedding[hashed_ids[row],:]
// rows = 32768, D = 1024 fp32 = 4096 B per row.
//
// R11: final cell of the (store width x cache hint) matrix.
// Measured: v4+cs = 27.2-27.3us (best), v4 plain = 28.4, v8 plain = 28.4,
// v4 wt = 28.5. Untested: v8+cs. 256-bit loads (evict_last, pins 40MB
// table in L2) and 256-bit evict-first stores halve instruction count
// while keeping the best-measured cache policy.
// Structure: 256 threads, 4 sub-groups of 64 lanes, 2 rows each
// (8 rows/block), int2 id fetch, MLP=4x32B gathers per thread.

static constexpr int THREADS = 256;
static constexpr int LANES = 64;          // threads per row
static constexpr int ROWS_PER_BLK = 8;
static constexpr int ROW_BYTES = 4096;

struct alignas(32) F8 { float4 lo, hi; };

__device__ __forceinline__ F8 ldg256_el(const char* p)
{
    F8 v;
    asm volatile("ld.global.nc.L2::evict_last.v8.f32 "
                 "{%0,%1,%2,%3,%4,%5,%6,%7}, [%8];"
                 : "=f"(v.lo.x), "=f"(v.lo.y), "=f"(v.lo.z), "=f"(v.lo.w),
                   "=f"(v.hi.x), "=f"(v.hi.y), "=f"(v.hi.z), "=f"(v.hi.w)
                 : "l"(p));
    return v;
}

__device__ __forceinline__ void stg256_cs(char* p, const F8& v)
{
    asm volatile("st.global.cs.v8.f32 [%0], {%1,%2,%3,%4,%5,%6,%7,%8};"
                 :: "l"(p),
                    "f"(v.lo.x), "f"(v.lo.y), "f"(v.lo.z), "f"(v.lo.w),
                    "f"(v.hi.x), "f"(v.hi.y), "f"(v.hi.z), "f"(v.hi.w)
                 : "memory");
}

__global__ void __launch_bounds__(THREADS)
hash_embedding_gather(const int* __restrict__ hashed_ids,
                      const char* __restrict__ emb,
                      char* __restrict__ out,
                      int nrows)
{
    int t    = threadIdx.x;
    int sub  = t >> 6;        // 0..3
    int lane = t & 63;        // 0..63

    int row0 = blockIdx.x * ROWS_PER_BLK + sub * 2;
    if (row0 >= nrows) return;

    // One 8-byte load fetches both ids (row0 even -> 8B aligned).
    int2 ids = *reinterpret_cast<const int2*>(hashed_ids + row0);

    const char* srcA = emb + (size_t)ids.x * ROW_BYTES + lane * 32;
    const char* srcB = emb + (size_t)ids.y * ROW_BYTES + lane * 32;
    char*       dstA = out + (size_t)row0       * ROW_BYTES + lane * 32;
    char*       dstB = out + (size_t)(row0 + 1) * ROW_BYTES + lane * 32;

    // 4 independent 32B gathers, front-batched (128B in flight/thread).
    F8 a0 = ldg256_el(srcA);
    F8 a1 = ldg256_el(srcA + LANES * 32);
    F8 b0 = ldg256_el(srcB);
    F8 b1 = ldg256_el(srcB + LANES * 32);

    // 256-bit evict-first stores (best-measured cache policy).
    stg256_cs(dstA,              a0);
    stg256_cs(dstA + LANES * 32, a1);
    stg256_cs(dstB,              b0);
    stg256_cs(dstB + LANES * 32, b1);
}

extern "C" void kernel_launch(void* const* d_in, const int* in_sizes, int n_in,
                              void* d_out, int out_size)
{
    // metadata order: input_ids (unused), hashed_ids (int32), embedding (fp32)
    const int*  hashed_ids = (const int*)d_in[1];
    const char* emb        = (const char*)d_in[2];
    char*       out        = (char*)d_out;

    int nrows = in_sizes[1];   // 32768
    int blocks = (nrows + ROWS_PER_BLK - 1) / ROWS_PER_BLK;

    hash_embedding_gather<<<blocks, THREADS>>>(hashed_ids, emb, out, nrows);
}